// round 9
// baseline (speedup 1.0000x reference)
#include <cuda_runtime.h>
#include <cuda_bf16.h>
#include <cstdint>

#define H_   96
#define W_   96
#define S_   9216
#define CIN  256
#define NH   8
#define DH   32

// attention operands produced by qkv GEMM
__device__ float         g_q[NH * S_ * DH];            // fp32 Q
__device__ __nv_bfloat16 g_khi[NH * S_ * DH];          // K split
__device__ __nv_bfloat16 g_klo[NH * S_ * DH];
__device__ __nv_bfloat16 g_vhi[NH * S_ * DH];          // V split
__device__ __nv_bfloat16 g_vlo[NH * S_ * DH];
// bf16 split GEMM inputs
__device__ __nv_bfloat16 g_xhi[S_ * CIN];   // x transposed: [s][c]
__device__ __nv_bfloat16 g_xlo[S_ * CIN];
__device__ __nv_bfloat16 g_wqhi[768 * CIN];
__device__ __nv_bfloat16 g_wqlo[768 * CIN];
__device__ __nv_bfloat16 g_wohi[CIN * CIN];
__device__ __nv_bfloat16 g_wolo[CIN * CIN];
__device__ __nv_bfloat16 g_ahi[S_ * CIN];   // attention out split: [s][c]
__device__ __nv_bfloat16 g_alo[S_ * CIN];

// ---------------------------------------------------------------------------
// helpers
// ---------------------------------------------------------------------------
__device__ __forceinline__ void cp16(void* sdst, const void* gsrc) {
    unsigned d = (unsigned)__cvta_generic_to_shared(sdst);
    asm volatile("cp.async.cg.shared.global [%0], [%1], 16;" :: "r"(d), "l"(gsrc));
}
__device__ __forceinline__ void cp_commit() {
    asm volatile("cp.async.commit_group;");
}
template<int N> __device__ __forceinline__ void cp_wait() {
    asm volatile("cp.async.wait_group %0;" :: "n"(N));
}
__device__ __forceinline__ void mma16816(float& d0, float& d1, float& d2, float& d3,
                                         unsigned a0, unsigned a1, unsigned a2, unsigned a3,
                                         unsigned b0, unsigned b1) {
    asm volatile(
        "mma.sync.aligned.m16n8k16.row.col.f32.bf16.bf16.f32 "
        "{%0,%1,%2,%3},{%4,%5,%6,%7},{%8,%9},{%0,%1,%2,%3};"
        : "+f"(d0), "+f"(d1), "+f"(d2), "+f"(d3)
        : "r"(a0), "r"(a1), "r"(a2), "r"(a3), "r"(b0), "r"(b1));
}
__device__ __forceinline__ void ldmx4(unsigned& r0, unsigned& r1, unsigned& r2, unsigned& r3,
                                      const __nv_bfloat16* p) {
    unsigned a = (unsigned)__cvta_generic_to_shared(p);
    asm volatile("ldmatrix.sync.aligned.m8n8.x4.shared.b16 {%0,%1,%2,%3}, [%4];"
                 : "=r"(r0), "=r"(r1), "=r"(r2), "=r"(r3) : "r"(a));
}
__device__ __forceinline__ void ldmx4t(unsigned& r0, unsigned& r1, unsigned& r2, unsigned& r3,
                                       const __nv_bfloat16* p) {
    unsigned a = (unsigned)__cvta_generic_to_shared(p);
    asm volatile("ldmatrix.sync.aligned.m8n8.x4.trans.shared.b16 {%0,%1,%2,%3}, [%4];"
                 : "=r"(r0), "=r"(r1), "=r"(r2), "=r"(r3) : "r"(a));
}
__device__ __forceinline__ void split_bf16(float v, __nv_bfloat16& hi, __nv_bfloat16& lo) {
    hi = __float2bfloat16_rn(v);
    lo = __float2bfloat16_rn(v - __bfloat162float(hi));
}
__device__ __forceinline__ float bf_res(float v) {
    return v - __bfloat162float(__float2bfloat16_rn(v));
}
__device__ __forceinline__ unsigned pack2bf(float x, float y) {
    __nv_bfloat162 t = __floats2bfloat162_rn(x, y);   // .x = low half
    return *reinterpret_cast<unsigned*>(&t);
}

// ---------------------------------------------------------------------------
// prep (merged): blocks [0, 2304): transpose+split x [C][S] -> xhi/xlo [S][C]
//                blocks [2304, 2368): split both weight matrices
// ---------------------------------------------------------------------------
#define NBX 2304   // (S_/32) * (CIN/32)

__global__ __launch_bounds__(256) void split_all_kernel(
    const float* __restrict__ x, const float* __restrict__ wq,
    const float* __restrict__ wo)
{
    __shared__ float tile[32][33];
    if (blockIdx.x < NBX) {
        const int m0 = (blockIdx.x % (S_ / 32)) * 32;   // s
        const int k0 = (blockIdx.x / (S_ / 32)) * 32;   // c
        const int tx = threadIdx.x & 31, ty = threadIdx.x >> 5;
#pragma unroll
        for (int i = 0; i < 4; i++)
            tile[ty + 8 * i][tx] = x[(k0 + ty + 8 * i) * S_ + m0 + tx];
        __syncthreads();
#pragma unroll
        for (int i = 0; i < 4; i++) {
            int row = ty + 8 * i;
            float v = tile[tx][row];
            __nv_bfloat16 hi, lo;
            split_bf16(v, hi, lo);
            g_xhi[(m0 + row) * CIN + k0 + tx] = hi;
            g_xlo[(m0 + row) * CIN + k0 + tx] = lo;
        }
    } else {
        const int NQ = 768 * CIN;
        const int NO = CIN * CIN;
        const int bid = blockIdx.x - NBX;
        for (int i = bid * 256 + threadIdx.x; i < NQ + NO; i += 64 * 256) {
            __nv_bfloat16 hi, lo;
            if (i < NQ) {
                split_bf16(wq[i], hi, lo);
                g_wqhi[i] = hi; g_wqlo[i] = lo;
            } else {
                int j = i - NQ;
                split_bf16(wo[j], hi, lo);
                g_wohi[j] = hi; g_wolo[j] = lo;
            }
        }
    }
}

// ---------------------------------------------------------------------------
// bf16x3 GEMM, 4-stage cp.async multistage, ONE __syncthreads per k-iter.
// C[m][n] = sum_k A[m][k]*B[n][k], M tile BM, N tile BN, K=256.
// EPI 0: write q fp32 / k,v bf16-split (m = s). EPI 1: NCHW fp32 (m = s, n = cout).
// ---------------------------------------------------------------------------
#define PITCH 24
#define NTILE 16
#define NS    4

template<int BM, int BN, int EPI>
__global__ __launch_bounds__(256, 2) void gemm_bf16x3(
    const __nv_bfloat16* __restrict__ Ahi, const __nv_bfloat16* __restrict__ Alo,
    const __nv_bfloat16* __restrict__ Bhi, const __nv_bfloat16* __restrict__ Blo,
    const float* __restrict__ bias, float* __restrict__ Cout)
{
    constexpr int NNT = BN / 32;         // n-tiles (of 8) per warp
    constexpr int NMT = BM / 32;         // m-tiles (of 16) per warp
    __shared__ __nv_bfloat16 SA[NS][2][BM][PITCH];
    __shared__ __nv_bfloat16 SB[NS][2][BN][PITCH];

    const int bm = blockIdx.x * BM;
    const int bn = blockIdx.y * BN;
    const int tid = threadIdx.x;
    const int lane = tid & 31, wid = tid >> 5;
    const int g = lane >> 2, t4 = lane & 3;
    const int mw = (wid & 1) * (BM / 2);
    const int nw = (wid >> 1) * (BN / 4);

    // ldmatrix per-lane offsets
    const int arow = (lane & 7) + ((lane >> 3) & 1) * 8;
    const int acol = (lane >> 4) * 8;
    const int brow = (lane & 7) + (lane >> 4) * 8;
    const int bcol = ((lane >> 3) & 1) * 8;

    float acc[NMT][NNT][4];
#pragma unroll
    for (int a = 0; a < NMT; a++)
#pragma unroll
        for (int b = 0; b < NNT; b++)
#pragma unroll
            for (int c = 0; c < 4; c++) acc[a][b][c] = 0.f;

    // generic staging: unit = (matrix, row, split, colchunk); A units first
    auto issue = [&](int t) {
        const int st = t & (NS - 1);
        const int k0 = t * 16;
        for (int u = tid; u < (BM + BN) * 4; u += 256) {
            const bool isB = u >= BM * 4;
            const int  v   = isB ? u - BM * 4 : u;
            const int  row = v >> 2;
            const int  sp  = (v >> 1) & 1;
            const int  cc  = v & 1;
            if (!isB) {
                const __nv_bfloat16* src = sp ? Alo : Ahi;
                cp16(&SA[st][sp][row][cc * 8],
                     src + (size_t)(bm + row) * CIN + k0 + cc * 8);
            } else {
                const __nv_bfloat16* src = sp ? Blo : Bhi;
                cp16(&SB[st][sp][row][cc * 8],
                     src + (size_t)(bn + row) * CIN + k0 + cc * 8);
            }
        }
    };

    // prologue: stages 0..NS-2
#pragma unroll
    for (int p = 0; p < NS - 1; p++) { issue(p); cp_commit(); }

    for (int t = 0; t < NTILE; t++) {
        const int st = t & (NS - 1);
        cp_wait<NS - 2>();
        __syncthreads();                 // stage t ready; stage t-1 free to overwrite
        if (t + NS - 1 < NTILE) issue(t + NS - 1);
        cp_commit();                     // empty commits keep group accounting exact

        unsigned bh[NNT][2], bl[NNT][2];
#pragma unroll
        for (int p = 0; p < NNT / 2; p++) {
            const __nv_bfloat16* ph = &SB[st][0][nw + 16 * p + brow][bcol];
            const __nv_bfloat16* pl = &SB[st][1][nw + 16 * p + brow][bcol];
            ldmx4(bh[2 * p][0], bh[2 * p][1], bh[2 * p + 1][0], bh[2 * p + 1][1], ph);
            ldmx4(bl[2 * p][0], bl[2 * p][1], bl[2 * p + 1][0], bl[2 * p + 1][1], pl);
        }
#pragma unroll
        for (int mt = 0; mt < NMT; mt++) {
            const __nv_bfloat16* pah = &SA[st][0][mw + 16 * mt + arow][acol];
            const __nv_bfloat16* pal = &SA[st][1][mw + 16 * mt + arow][acol];
            unsigned ah0, ah1, ah2, ah3, al0, al1, al2, al3;
            ldmx4(ah0, ah1, ah2, ah3, pah);
            ldmx4(al0, al1, al2, al3, pal);
#pragma unroll
            for (int nt = 0; nt < NNT; nt++) {
                float* d = acc[mt][nt];
                mma16816(d[0], d[1], d[2], d[3], ah0, ah1, ah2, ah3, bh[nt][0], bh[nt][1]);
                mma16816(d[0], d[1], d[2], d[3], ah0, ah1, ah2, ah3, bl[nt][0], bl[nt][1]);
                mma16816(d[0], d[1], d[2], d[3], al0, al1, al2, al3, bh[nt][0], bh[nt][1]);
            }
        }
    }

#pragma unroll
    for (int mt = 0; mt < NMT; mt++) {
#pragma unroll
        for (int nt = 0; nt < NNT; nt++) {
            int m0 = bm + mw + 16 * mt + g;
            int n0 = bn + nw + 8 * nt + 2 * t4;
            float b0 = bias[n0], b1 = bias[n0 + 1];
            float* d = acc[mt][nt];
            float v0 = d[0] + b0, v1 = d[1] + b1;
            float v2 = d[2] + b0, v3 = d[3] + b1;
            if (EPI == 0) {
                int sel = n0 >> 8;
                int hh = (n0 >> 5) & 7;
                int dd = n0 & 31;
                size_t i0 = ((size_t)hh * S_ + m0) * DH + dd;
                size_t i1 = i0 + 8 * DH;
                if (sel == 0) {
                    *(float2*)&g_q[i0] = make_float2(v0, v1);
                    *(float2*)&g_q[i1] = make_float2(v2, v3);
                } else if (sel == 1) {
                    *(unsigned*)&g_khi[i0] = pack2bf(v0, v1);
                    *(unsigned*)&g_klo[i0] = pack2bf(bf_res(v0), bf_res(v1));
                    *(unsigned*)&g_khi[i1] = pack2bf(v2, v3);
                    *(unsigned*)&g_klo[i1] = pack2bf(bf_res(v2), bf_res(v3));
                } else {
                    *(unsigned*)&g_vhi[i0] = pack2bf(v0, v1);
                    *(unsigned*)&g_vlo[i0] = pack2bf(bf_res(v0), bf_res(v1));
                    *(unsigned*)&g_vhi[i1] = pack2bf(v2, v3);
                    *(unsigned*)&g_vlo[i1] = pack2bf(bf_res(v2), bf_res(v3));
                }
            } else {
                Cout[(size_t)n0 * S_ + m0]           = v0;
                Cout[(size_t)(n0 + 1) * S_ + m0]     = v1;
                Cout[(size_t)n0 * S_ + m0 + 8]       = v2;
                Cout[(size_t)(n0 + 1) * S_ + m0 + 8] = v3;
            }
        }
    }
}

// ---------------------------------------------------------------------------
// MMA neighborhood attention (unchanged).
// ---------------------------------------------------------------------------
#define TQX    16
#define TQY    8
#define WINX   22
#define NPOS   308
#define PQK    40
#define SK_ELE (NPOS * PQK)
#define NATTEN_SMEM (4 * SK_ELE * 2)

__global__ __launch_bounds__(256, 2) void natten_mma()
{
    extern __shared__ __nv_bfloat16 sm[];
    __nv_bfloat16* skh = sm;
    __nv_bfloat16* skl = sm + SK_ELE;
    __nv_bfloat16* svh = sm + 2 * SK_ELE;
    __nv_bfloat16* svl = sm + 3 * SK_ELE;

    const int h = blockIdx.z;
    const int qx0 = blockIdx.x * TQX, qy0 = blockIdx.y * TQY;
    const int wx0 = min(max(qx0 - 3, 0), W_ - WINX);
    const int wy0 = min(max(qy0 - 3, 0), H_ - 14);
    const int tid = threadIdx.x;
    const int lane = tid & 31, wid = tid >> 5;
    const int g = lane >> 2, t4 = lane & 3;
    const int lrow = lane & 7, lmat = lane >> 3;
    const float scale = 0.17677669529663687f;

    const size_t hb = (size_t)h * S_ * DH;

    {
        const __nv_bfloat16* Kh = g_khi + hb;
        const __nv_bfloat16* Kl = g_klo + hb;
        for (int c = tid; c < NPOS * 4; c += 256) {
            int p = c >> 2, off = (c & 3) * 8;
            int gy = wy0 + p / WINX, gx = wx0 + p % WINX;
            size_t gi = (size_t)(gy * W_ + gx) * DH + off;
            cp16(&skh[p * PQK + off], Kh + gi);
            cp16(&skl[p * PQK + off], Kl + gi);
        }
        cp_commit();
        const __nv_bfloat16* Vh = g_vhi + hb;
        const __nv_bfloat16* Vl = g_vlo + hb;
        for (int c = tid; c < NPOS * 4; c += 256) {
            int p = c >> 2, off = (c & 3) * 8;
            int gy = wy0 + p / WINX, gx = wx0 + p % WINX;
            size_t gi = (size_t)(gy * W_ + gx) * DH + off;
            cp16(&svh[p * PQK + off], Vh + gi);
            cp16(&svl[p * PQK + off], Vl + gi);
        }
        cp_commit();
    }

    const int wxq = (wid & 1) * 8;
    const int wyq = (wid >> 1) * 2;
    const int qxg = qx0 + wxq + g;
    const int qyg0 = qy0 + wyq, qyg1 = qyg0 + 1;

    const int cxs = min(max(qx0 + wxq, 3), W_ - 4);
    const int cys = min(max(qyg0, 3), H_ - 4);
    const int bx0 = min((cxs - 3 - wx0) & ~1, 6);
    const int by0 = min(cys - 3 - wy0, 6);

    const int cx = min(max(qxg, 3), W_ - 4);
    const int cy0 = min(max(qyg0, 3), H_ - 4);
    const int cy1 = min(max(qyg1, 3), H_ - 4);
    const int vx  = cx - 3 - wx0 - bx0;
    const int vy0 = cy0 - 3 - wy0 - by0;
    const int vy1 = cy1 - 3 - wy0 - by0;

    const float* Qb = g_q + hb;
    unsigned qa_h[2][4], qa_l[2][4];
    {
        const size_t s0 = (size_t)(qyg0 * W_ + qxg) * DH;
        const size_t s1 = (size_t)(qyg1 * W_ + qxg) * DH;
#pragma unroll
        for (int kc = 0; kc < 2; kc++) {
            float2 u0 = *(const float2*)&Qb[s0 + kc * 16 + 2 * t4];
            float2 u1 = *(const float2*)&Qb[s1 + kc * 16 + 2 * t4];
            float2 w0 = *(const float2*)&Qb[s0 + kc * 16 + 8 + 2 * t4];
            float2 w1 = *(const float2*)&Qb[s1 + kc * 16 + 8 + 2 * t4];
            u0.x *= scale; u0.y *= scale; u1.x *= scale; u1.y *= scale;
            w0.x *= scale; w0.y *= scale; w1.x *= scale; w1.y *= scale;
            qa_h[kc][0] = pack2bf(u0.x, u0.y);
            qa_h[kc][1] = pack2bf(u1.x, u1.y);
            qa_h[kc][2] = pack2bf(w0.x, w0.y);
            qa_h[kc][3] = pack2bf(w1.x, w1.y);
            qa_l[kc][0] = pack2bf(bf_res(u0.x), bf_res(u0.y));
            qa_l[kc][1] = pack2bf(bf_res(u1.x), bf_res(u1.y));
            qa_l[kc][2] = pack2bf(bf_res(w0.x), bf_res(w0.y));
            qa_l[kc][3] = pack2bf(bf_res(w1.x), bf_res(w1.y));
        }
    }

    cp_wait<1>();
    __syncthreads();

    const int kcol = (lmat & 1) * 8 + (lmat >> 1) * 16;
    float acc[16][4];
#pragma unroll
    for (int nt = 0; nt < 16; nt++)
#pragma unroll
        for (int e = 0; e < 4; e++) acc[nt][e] = 0.f;

#pragma unroll
    for (int nt = 0; nt < 16; nt++) {
        const int pos0 = (by0 + (nt >> 1)) * WINX + bx0 + (nt & 1) * 8;
        unsigned bh0, bh1, bh2, bh3, bl0, bl1, bl2, bl3;
        ldmx4(bh0, bh1, bh2, bh3, &skh[(pos0 + lrow) * PQK + kcol]);
        ldmx4(bl0, bl1, bl2, bl3, &skl[(pos0 + lrow) * PQK + kcol]);
        float* d = acc[nt];
        mma16816(d[0], d[1], d[2], d[3], qa_h[0][0], qa_h[0][1], qa_h[0][2], qa_h[0][3], bh0, bh1);
        mma16816(d[0], d[1], d[2], d[3], qa_h[1][0], qa_h[1][1], qa_h[1][2], qa_h[1][3], bh2, bh3);
        mma16816(d[0], d[1], d[2], d[3], qa_h[0][0], qa_h[0][1], qa_h[0][2], qa_h[0][3], bl0, bl1);
        mma16816(d[0], d[1], d[2], d[3], qa_h[1][0], qa_h[1][1], qa_h[1][2], qa_h[1][3], bl2, bl3);
        mma16816(d[0], d[1], d[2], d[3], qa_l[0][0], qa_l[0][1], qa_l[0][2], qa_l[0][3], bh0, bh1);
        mma16816(d[0], d[1], d[2], d[3], qa_l[1][0], qa_l[1][1], qa_l[1][2], qa_l[1][3], bh2, bh3);
    }

    float mx0 = -1e30f, mx1 = -1e30f;
#pragma unroll
    for (int nt = 0; nt < 16; nt++) {
        const int jy = nt >> 1;
        const int jxb = (nt & 1) * 8 + 2 * t4;
#pragma unroll
        for (int e = 0; e < 2; e++) {
            const int jx = jxb + e;
            bool okx = (unsigned)(jx - vx) < 7u;
            bool ok0 = okx && ((unsigned)(jy - vy0) < 7u);
            bool ok1 = okx && ((unsigned)(jy - vy1) < 7u);
            acc[nt][e]     = ok0 ? acc[nt][e]     : -1e30f;
            acc[nt][2 + e] = ok1 ? acc[nt][2 + e] : -1e30f;
            mx0 = fmaxf(mx0, acc[nt][e]);
            mx1 = fmaxf(mx1, acc[nt][2 + e]);
        }
    }
    mx0 = fmaxf(mx0, __shfl_xor_sync(0xffffffffu, mx0, 1));
    mx0 = fmaxf(mx0, __shfl_xor_sync(0xffffffffu, mx0, 2));
    mx1 = fmaxf(mx1, __shfl_xor_sync(0xffffffffu, mx1, 1));
    mx1 = fmaxf(mx1, __shfl_xor_sync(0xffffffffu, mx1, 2));

    float sum0 = 0.f, sum1 = 0.f;
#pragma unroll
    for (int nt = 0; nt < 16; nt++) {
#pragma unroll
        for (int e = 0; e < 2; e++) {
            float p0 = __expf(acc[nt][e] - mx0);
            float p1 = __expf(acc[nt][2 + e] - mx1);
            acc[nt][e] = p0; acc[nt][2 + e] = p1;
            sum0 += p0; sum1 += p1;
        }
    }
    sum0 += __shfl_xor_sync(0xffffffffu, sum0, 1);
    sum0 += __shfl_xor_sync(0xffffffffu, sum0, 2);
    sum1 += __shfl_xor_sync(0xffffffffu, sum1, 1);
    sum1 += __shfl_xor_sync(0xffffffffu, sum1, 2);
    const float inv0 = 1.0f / sum0, inv1 = 1.0f / sum1;

#pragma unroll
    for (int nt = 0; nt < 16; nt++) {
        float p00 = acc[nt][0], p01 = acc[nt][1];
        float p10 = acc[nt][2], p11 = acc[nt][3];
        unsigned hh0 = pack2bf(p00, p01);
        unsigned hh1 = pack2bf(p10, p11);
        unsigned ll0 = pack2bf(bf_res(p00), bf_res(p01));
        unsigned ll1 = pack2bf(bf_res(p10), bf_res(p11));
        acc[nt][0] = __uint_as_float(hh0);
        acc[nt][1] = __uint_as_float(hh1);
        acc[nt][2] = __uint_as_float(ll0);
        acc[nt][3] = __uint_as_float(ll1);
    }

    cp_wait<0>();
    __syncthreads();

    float o[4][4];
#pragma unroll
    for (int vt = 0; vt < 4; vt++)
#pragma unroll
        for (int e = 0; e < 4; e++) o[vt][e] = 0.f;

    const int vrow = (lmat & 1) * 8 + lrow;
    const int vmat = (lmat >> 1) * 8;
#pragma unroll
    for (int kt = 0; kt < 8; kt++) {
        const int prow = (by0 + kt) * WINX + bx0;
        unsigned ah0 = __float_as_uint(acc[2 * kt][0]);
        unsigned ah1 = __float_as_uint(acc[2 * kt][1]);
        unsigned ah2 = __float_as_uint(acc[2 * kt + 1][0]);
        unsigned ah3 = __float_as_uint(acc[2 * kt + 1][1]);
        unsigned al0 = __float_as_uint(acc[2 * kt][2]);
        unsigned al1 = __float_as_uint(acc[2 * kt][3]);
        unsigned al2 = __float_as_uint(acc[2 * kt + 1][2]);
        unsigned al3 = __float_as_uint(acc[2 * kt + 1][3]);
#pragma unroll
        for (int half = 0; half < 2; half++) {
            unsigned bh0, bh1, bh2, bh3, bl0, bl1, bl2, bl3;
            const int col = half * 16 + vmat;
            ldmx4t(bh0, bh1, bh2, bh3, &svh[(prow + vrow) * PQK + col]);
            ldmx4t(bl0, bl1, bl2, bl3, &svl[(prow + vrow) * PQK + col]);
            float* d0 = o[2 * half];
            float* d1 = o[2 * half + 1];
            mma16816(d0[0], d0[1], d0[2], d0[3], ah0, ah1, ah2, ah3, bh0, bh1);
            mma16816(d0[0], d0[1], d0[2], d0[3], ah0, ah1, ah2, ah3, bl0, bl1);
            mma16816(d0[0], d0[1], d0[2], d0[3], al0, al1, al2, al3, bh0, bh1);
            mma16816(d1[0], d1[1], d1[2], d1[3], ah0, ah1, ah2, ah3, bh2, bh3);
            mma16816(d1[0], d1[1], d1[2], d1[3], ah0, ah1, ah2, ah3, bl2, bl3);
            mma16816(d1[0], d1[1], d1[2], d1[3], al0, al1, al2, al3, bh2, bh3);
        }
    }

    {
        size_t s0 = (size_t)(qyg0 * W_ + qxg) * CIN + h * DH;
        size_t s1 = (size_t)(qyg1 * W_ + qxg) * CIN + h * DH;
#pragma unroll
        for (int vt = 0; vt < 4; vt++) {
            int c = vt * 8 + 2 * t4;
            float f00 = o[vt][0] * inv0, f01 = o[vt][1] * inv0;
            float f10 = o[vt][2] * inv1, f11 = o[vt][3] * inv1;
            *(unsigned*)&g_ahi[s0 + c] = pack2bf(f00, f01);
            *(unsigned*)&g_alo[s0 + c] = pack2bf(bf_res(f00), bf_res(f01));
            *(unsigned*)&g_ahi[s1 + c] = pack2bf(f10, f11);
            *(unsigned*)&g_alo[s1 + c] = pack2bf(bf_res(f10), bf_res(f11));
        }
    }
}

// ---------------------------------------------------------------------------
extern "C" void kernel_launch(void* const* d_in, const int* in_sizes, int n_in,
                              void* d_out, int out_size)
{
    const float* x     = (const float*)d_in[0];   // [256][9216]
    const float* w_qkv = (const float*)d_in[1];   // [768][256]
    const float* b_qkv = (const float*)d_in[2];   // [768]
    const float* w_out = (const float*)d_in[3];   // [256][256]
    const float* b_out = (const float*)d_in[4];   // [256]
    float* out = (float*)d_out;                   // [256][9216]

    cudaFuncSetAttribute(natten_mma,
                         cudaFuncAttributeMaxDynamicSharedMemorySize, NATTEN_SMEM);

    split_all_kernel<<<NBX + 64, 256>>>(x, w_qkv, w_out);

    __nv_bfloat16 *xhi, *xlo, *wqhi, *wqlo, *wohi, *wolo, *ahi, *alo;
    cudaGetSymbolAddress((void**)&xhi,  g_xhi);
    cudaGetSymbolAddress((void**)&xlo,  g_xlo);
    cudaGetSymbolAddress((void**)&wqhi, g_wqhi);
    cudaGetSymbolAddress((void**)&wqlo, g_wqlo);
    cudaGetSymbolAddress((void**)&wohi, g_wohi);
    cudaGetSymbolAddress((void**)&wolo, g_wolo);
    cudaGetSymbolAddress((void**)&ahi,  g_ahi);
    cudaGetSymbolAddress((void**)&alo,  g_alo);

    // qkv: M = s (128-tiles, 72), N = 768 channels (128-tiles, 6)
    gemm_bf16x3<128, 128, 0><<<dim3(S_ / 128, 768 / 128), 256>>>(
        xhi, xlo, wqhi, wqlo, b_qkv, nullptr);

    natten_mma<<<dim3(W_ / TQX, H_ / TQY, NH), 256, NATTEN_SMEM>>>();

    // out: M = s (64-tiles, 144), N = cout (128-tiles, 2) -> 288 blocks, 2 CTA/SM
    gemm_bf16x3<64, 128, 1><<<dim3(S_ / 64, CIN / 128), 256>>>(
        ahi, alo, wohi, wolo, b_out, out);
}

// round 10
// speedup vs baseline: 1.0532x; 1.0532x over previous
#include <cuda_runtime.h>
#include <cuda_bf16.h>
#include <cstdint>

#define H_   96
#define W_   96
#define S_   9216
#define CIN  256
#define NH   8
#define DH   32

// attention operands produced by qkv GEMM (all bf16 hi/lo split; q pre-scaled)
__device__ __nv_bfloat16 g_qhi[NH * S_ * DH];
__device__ __nv_bfloat16 g_qlo[NH * S_ * DH];
__device__ __nv_bfloat16 g_khi[NH * S_ * DH];
__device__ __nv_bfloat16 g_klo[NH * S_ * DH];
__device__ __nv_bfloat16 g_vhi[NH * S_ * DH];
__device__ __nv_bfloat16 g_vlo[NH * S_ * DH];
// bf16 split GEMM inputs
__device__ __nv_bfloat16 g_xhi[S_ * CIN];   // x transposed: [s][c]
__device__ __nv_bfloat16 g_xlo[S_ * CIN];
__device__ __nv_bfloat16 g_wqhi[768 * CIN];
__device__ __nv_bfloat16 g_wqlo[768 * CIN];
__device__ __nv_bfloat16 g_wohi[CIN * CIN];
__device__ __nv_bfloat16 g_wolo[CIN * CIN];
__device__ __nv_bfloat16 g_ahi[S_ * CIN];   // attention out split: [s][c]
__device__ __nv_bfloat16 g_alo[S_ * CIN];

// ---------------------------------------------------------------------------
// helpers
// ---------------------------------------------------------------------------
__device__ __forceinline__ void cp16(void* sdst, const void* gsrc) {
    unsigned d = (unsigned)__cvta_generic_to_shared(sdst);
    asm volatile("cp.async.cg.shared.global [%0], [%1], 16;" :: "r"(d), "l"(gsrc));
}
__device__ __forceinline__ void cp_commit() {
    asm volatile("cp.async.commit_group;");
}
template<int N> __device__ __forceinline__ void cp_wait() {
    asm volatile("cp.async.wait_group %0;" :: "n"(N));
}
__device__ __forceinline__ void mma16816(float& d0, float& d1, float& d2, float& d3,
                                         unsigned a0, unsigned a1, unsigned a2, unsigned a3,
                                         unsigned b0, unsigned b1) {
    asm volatile(
        "mma.sync.aligned.m16n8k16.row.col.f32.bf16.bf16.f32 "
        "{%0,%1,%2,%3},{%4,%5,%6,%7},{%8,%9},{%0,%1,%2,%3};"
        : "+f"(d0), "+f"(d1), "+f"(d2), "+f"(d3)
        : "r"(a0), "r"(a1), "r"(a2), "r"(a3), "r"(b0), "r"(b1));
}
__device__ __forceinline__ void ldmx4(unsigned& r0, unsigned& r1, unsigned& r2, unsigned& r3,
                                      const __nv_bfloat16* p) {
    unsigned a = (unsigned)__cvta_generic_to_shared(p);
    asm volatile("ldmatrix.sync.aligned.m8n8.x4.shared.b16 {%0,%1,%2,%3}, [%4];"
                 : "=r"(r0), "=r"(r1), "=r"(r2), "=r"(r3) : "r"(a));
}
__device__ __forceinline__ void ldmx4t(unsigned& r0, unsigned& r1, unsigned& r2, unsigned& r3,
                                       const __nv_bfloat16* p) {
    unsigned a = (unsigned)__cvta_generic_to_shared(p);
    asm volatile("ldmatrix.sync.aligned.m8n8.x4.trans.shared.b16 {%0,%1,%2,%3}, [%4];"
                 : "=r"(r0), "=r"(r1), "=r"(r2), "=r"(r3) : "r"(a));
}
__device__ __forceinline__ void split_bf16(float v, __nv_bfloat16& hi, __nv_bfloat16& lo) {
    hi = __float2bfloat16_rn(v);
    lo = __float2bfloat16_rn(v - __bfloat162float(hi));
}
__device__ __forceinline__ float bf_res(float v) {
    return v - __bfloat162float(__float2bfloat16_rn(v));
}
__device__ __forceinline__ unsigned pack2bf(float x, float y) {
    __nv_bfloat162 t = __floats2bfloat162_rn(x, y);   // .x = low half
    return *reinterpret_cast<unsigned*>(&t);
}
__device__ __forceinline__ unsigned ldg32(const __nv_bfloat16* p) {
    return *reinterpret_cast<const unsigned*>(p);
}

// ---------------------------------------------------------------------------
// prep (merged): blocks [0, 2304): transpose+split x [C][S] -> xhi/xlo [S][C]
//                blocks [2304, 2368): split both weight matrices
// ---------------------------------------------------------------------------
#define NBX 2304   // (S_/32) * (CIN/32)

__global__ __launch_bounds__(256) void split_all_kernel(
    const float* __restrict__ x, const float* __restrict__ wq,
    const float* __restrict__ wo)
{
    __shared__ float tile[32][33];
    if (blockIdx.x < NBX) {
        const int m0 = (blockIdx.x % (S_ / 32)) * 32;   // s
        const int k0 = (blockIdx.x / (S_ / 32)) * 32;   // c
        const int tx = threadIdx.x & 31, ty = threadIdx.x >> 5;
#pragma unroll
        for (int i = 0; i < 4; i++)
            tile[ty + 8 * i][tx] = x[(k0 + ty + 8 * i) * S_ + m0 + tx];
        __syncthreads();
#pragma unroll
        for (int i = 0; i < 4; i++) {
            int row = ty + 8 * i;
            float v = tile[tx][row];
            __nv_bfloat16 hi, lo;
            split_bf16(v, hi, lo);
            g_xhi[(m0 + row) * CIN + k0 + tx] = hi;
            g_xlo[(m0 + row) * CIN + k0 + tx] = lo;
        }
    } else {
        const int NQ = 768 * CIN;
        const int NO = CIN * CIN;
        const int bid = blockIdx.x - NBX;
        for (int i = bid * 256 + threadIdx.x; i < NQ + NO; i += 64 * 256) {
            __nv_bfloat16 hi, lo;
            if (i < NQ) {
                split_bf16(wq[i], hi, lo);
                g_wqhi[i] = hi; g_wqlo[i] = lo;
            } else {
                int j = i - NQ;
                split_bf16(wo[j], hi, lo);
                g_wohi[j] = hi; g_wolo[j] = lo;
            }
        }
    }
}

// ---------------------------------------------------------------------------
// bf16x3 GEMM, 4-stage cp.async multistage, ONE __syncthreads per k-iter.
// C[m][n] = sum_k A[m][k]*B[n][k], M tile 128, N tile BN, K=256.
// EPI 0: write q (scaled) / k / v bf16-split (BN=128). EPI 1: NCHW fp32 (BN=64).
// ---------------------------------------------------------------------------
#define PITCH 24
#define NTILE 16
#define NS    4

template<int BN, int EPI>
__global__ __launch_bounds__(256, 2) void gemm_bf16x3(
    const __nv_bfloat16* __restrict__ Ahi, const __nv_bfloat16* __restrict__ Alo,
    const __nv_bfloat16* __restrict__ Bhi, const __nv_bfloat16* __restrict__ Blo,
    const float* __restrict__ bias, float* __restrict__ Cout)
{
    constexpr int NNT = BN / 32;         // n-tiles (of 8) per warp
    __shared__ __nv_bfloat16 SA[NS][2][128][PITCH];
    __shared__ __nv_bfloat16 SB[NS][2][BN][PITCH];

    const int bm = blockIdx.x * 128;
    const int bn = blockIdx.y * BN;
    const int tid = threadIdx.x;
    const int lane = tid & 31, wid = tid >> 5;
    const int g = lane >> 2, t4 = lane & 3;
    const int mw = (wid & 1) * 64;
    const int nw = (wid >> 1) * (BN / 4);

    // ldmatrix per-lane offsets
    const int arow = (lane & 7) + ((lane >> 3) & 1) * 8;
    const int acol = (lane >> 4) * 8;
    const int brow = (lane & 7) + (lane >> 4) * 8;
    const int bcol = ((lane >> 3) & 1) * 8;

    // loaders
    const int lr = tid >> 1;
    const int lc = (tid & 1) * 8;

    float acc[4][NNT][4];
#pragma unroll
    for (int a = 0; a < 4; a++)
#pragma unroll
        for (int b = 0; b < NNT; b++)
#pragma unroll
            for (int c = 0; c < 4; c++) acc[a][b][c] = 0.f;

    auto issue = [&](int t) {
        int st = t & (NS - 1);
        int k0 = t * 16;
        cp16(&SA[st][0][lr][lc], Ahi + (size_t)(bm + lr) * CIN + k0 + lc);
        cp16(&SA[st][1][lr][lc], Alo + (size_t)(bm + lr) * CIN + k0 + lc);
        if (BN == 128 || tid < 128) {
            cp16(&SB[st][0][lr][lc], Bhi + (size_t)(bn + lr) * CIN + k0 + lc);
            cp16(&SB[st][1][lr][lc], Blo + (size_t)(bn + lr) * CIN + k0 + lc);
        }
    };

    // prologue: stages 0..NS-2
#pragma unroll
    for (int p = 0; p < NS - 1; p++) { issue(p); cp_commit(); }

    for (int t = 0; t < NTILE; t++) {
        const int st = t & (NS - 1);
        cp_wait<NS - 2>();
        __syncthreads();                 // stage t ready; stage t-1 free to overwrite
        if (t + NS - 1 < NTILE) issue(t + NS - 1);
        cp_commit();                     // empty commits keep group accounting exact

        unsigned bh[NNT][2], bl[NNT][2];
#pragma unroll
        for (int p = 0; p < NNT / 2; p++) {
            const __nv_bfloat16* ph = &SB[st][0][nw + 16 * p + brow][bcol];
            const __nv_bfloat16* pl = &SB[st][1][nw + 16 * p + brow][bcol];
            ldmx4(bh[2 * p][0], bh[2 * p][1], bh[2 * p + 1][0], bh[2 * p + 1][1], ph);
            ldmx4(bl[2 * p][0], bl[2 * p][1], bl[2 * p + 1][0], bl[2 * p + 1][1], pl);
        }
#pragma unroll
        for (int mt = 0; mt < 4; mt++) {
            const __nv_bfloat16* pah = &SA[st][0][mw + 16 * mt + arow][acol];
            const __nv_bfloat16* pal = &SA[st][1][mw + 16 * mt + arow][acol];
            unsigned ah0, ah1, ah2, ah3, al0, al1, al2, al3;
            ldmx4(ah0, ah1, ah2, ah3, pah);
            ldmx4(al0, al1, al2, al3, pal);
#pragma unroll
            for (int nt = 0; nt < NNT; nt++) {
                float* d = acc[mt][nt];
                mma16816(d[0], d[1], d[2], d[3], ah0, ah1, ah2, ah3, bh[nt][0], bh[nt][1]);
                mma16816(d[0], d[1], d[2], d[3], ah0, ah1, ah2, ah3, bl[nt][0], bl[nt][1]);
                mma16816(d[0], d[1], d[2], d[3], al0, al1, al2, al3, bh[nt][0], bh[nt][1]);
            }
        }
    }

    const float qscale = 0.17677669529663687f;  // 1/sqrt(32)
#pragma unroll
    for (int mt = 0; mt < 4; mt++) {
#pragma unroll
        for (int nt = 0; nt < NNT; nt++) {
            int m0 = bm + mw + 16 * mt + g;
            int n0 = bn + nw + 8 * nt + 2 * t4;
            float b0 = bias[n0], b1 = bias[n0 + 1];
            float* d = acc[mt][nt];
            float v0 = d[0] + b0, v1 = d[1] + b1;
            float v2 = d[2] + b0, v3 = d[3] + b1;
            if (EPI == 0) {
                int sel = n0 >> 8;
                int hh = (n0 >> 5) & 7;
                int dd = n0 & 31;
                size_t i0 = ((size_t)hh * S_ + m0) * DH + dd;
                size_t i1 = i0 + 8 * DH;
                __nv_bfloat16 *ph, *pl;
                if (sel == 0) {
                    v0 *= qscale; v1 *= qscale; v2 *= qscale; v3 *= qscale;
                    ph = g_qhi; pl = g_qlo;
                } else if (sel == 1) {
                    ph = g_khi; pl = g_klo;
                } else {
                    ph = g_vhi; pl = g_vlo;
                }
                *(unsigned*)&ph[i0] = pack2bf(v0, v1);
                *(unsigned*)&pl[i0] = pack2bf(bf_res(v0), bf_res(v1));
                *(unsigned*)&ph[i1] = pack2bf(v2, v3);
                *(unsigned*)&pl[i1] = pack2bf(bf_res(v2), bf_res(v3));
            } else {
                Cout[(size_t)n0 * S_ + m0]           = v0;
                Cout[(size_t)(n0 + 1) * S_ + m0]     = v1;
                Cout[(size_t)n0 * S_ + m0 + 8]       = v2;
                Cout[(size_t)(n0 + 1) * S_ + m0 + 8] = v3;
            }
        }
    }
}

// ---------------------------------------------------------------------------
// MMA neighborhood attention, v4: 2x8 query subtile per warp.
// 256 threads / 8 warps, 16x8 query tile per block, one head.
// Warp owns 2(x) x 8(y) queries; m16 row r -> query (x = r>>3, y = r&7).
// Warp key window: 14 rows x 8 cols = 112 positions (QK 14 n-tiles, PV 7 k-tiles).
// K/V staged via cp.async from pre-split bf16; Q fragments loaded directly
// from pre-split, pre-scaled bf16 gmem.
// ---------------------------------------------------------------------------
#define TQX    16
#define TQY    8
#define WINX   22
#define NPOS   308
#define PQK    40
#define SK_ELE (NPOS * PQK)
#define NATTEN_SMEM (4 * SK_ELE * 2)

__global__ __launch_bounds__(256, 2) void natten_mma()
{
    extern __shared__ __nv_bfloat16 sm[];
    __nv_bfloat16* skh = sm;
    __nv_bfloat16* skl = sm + SK_ELE;
    __nv_bfloat16* svh = sm + 2 * SK_ELE;
    __nv_bfloat16* svl = sm + 3 * SK_ELE;

    const int h = blockIdx.z;
    const int qx0 = blockIdx.x * TQX, qy0 = blockIdx.y * TQY;
    const int wx0 = min(max(qx0 - 3, 0), W_ - WINX);
    const int wy0 = min(max(qy0 - 3, 0), H_ - 14);
    const int tid = threadIdx.x;
    const int lane = tid & 31, wid = tid >> 5;
    const int g = lane >> 2, t4 = lane & 3;
    const int lrow = lane & 7, lmat = lane >> 3;

    const size_t hb = (size_t)h * S_ * DH;

    // ---- stage K then V via cp.async (2 groups) ----
    {
        const __nv_bfloat16* Kh = g_khi + hb;
        const __nv_bfloat16* Kl = g_klo + hb;
        for (int c = tid; c < NPOS * 4; c += 256) {
            int p = c >> 2, off = (c & 3) * 8;
            int gy = wy0 + p / WINX, gx = wx0 + p % WINX;
            size_t gi = (size_t)(gy * W_ + gx) * DH + off;
            cp16(&skh[p * PQK + off], Kh + gi);
            cp16(&skl[p * PQK + off], Kl + gi);
        }
        cp_commit();
        const __nv_bfloat16* Vh = g_vhi + hb;
        const __nv_bfloat16* Vl = g_vlo + hb;
        for (int c = tid; c < NPOS * 4; c += 256) {
            int p = c >> 2, off = (c & 3) * 8;
            int gy = wy0 + p / WINX, gx = wx0 + p % WINX;
            size_t gi = (size_t)(gy * W_ + gx) * DH + off;
            cp16(&svh[p * PQK + off], Vh + gi);
            cp16(&svl[p * PQK + off], Vl + gi);
        }
        cp_commit();
    }

    // warp query subtile: 2 in x, 8 in y
    const int wxq  = wid * 2;
    const int qxg0 = qx0 + wxq, qxg1 = qxg0 + 1;
    const int qyg  = qy0 + g;             // this thread's query y (both rows)

    // warp x-window origin (8 wide) inside block window; clamp to fit
    const int bx0 = min(min(max(qxg0, 3), W_ - 4) - 3 - wx0, WINX - 8);
    // per-thread valid ranges
    const int vy  = min(max(qyg, 3), H_ - 4) - 3 - wy0;      // jy in [vy, vy+7)
    const int vx0 = min(max(qxg0, 3), W_ - 4) - 3 - wx0 - bx0;
    const int vx1 = min(max(qxg1, 3), W_ - 4) - 3 - wx0 - bx0;

    // ---- Q fragments from pre-split bf16 gmem (overlaps cp.async) ----
    unsigned qa_h[2][4], qa_l[2][4];
    {
        const __nv_bfloat16* Qh = g_qhi + hb;
        const __nv_bfloat16* Ql = g_qlo + hb;
        const size_t s0 = (size_t)(qyg * W_ + qxg0) * DH;
        const size_t s1 = s0 + DH;   // query x+1
#pragma unroll
        for (int kc = 0; kc < 2; kc++) {
            qa_h[kc][0] = ldg32(&Qh[s0 + kc * 16 + 2 * t4]);
            qa_h[kc][1] = ldg32(&Qh[s1 + kc * 16 + 2 * t4]);
            qa_h[kc][2] = ldg32(&Qh[s0 + kc * 16 + 8 + 2 * t4]);
            qa_h[kc][3] = ldg32(&Qh[s1 + kc * 16 + 8 + 2 * t4]);
            qa_l[kc][0] = ldg32(&Ql[s0 + kc * 16 + 2 * t4]);
            qa_l[kc][1] = ldg32(&Ql[s1 + kc * 16 + 2 * t4]);
            qa_l[kc][2] = ldg32(&Ql[s0 + kc * 16 + 8 + 2 * t4]);
            qa_l[kc][3] = ldg32(&Ql[s1 + kc * 16 + 8 + 2 * t4]);
        }
    }

    cp_wait<1>();     // K staged (V may still be in flight)
    __syncthreads();

    // ---- QK MMA: 14 n-tiles of 8 (one window row each) ----
    const int kcol = (lmat & 1) * 8 + (lmat >> 1) * 16;
    float acc[14][4];
#pragma unroll
    for (int nt = 0; nt < 14; nt++)
#pragma unroll
        for (int e = 0; e < 4; e++) acc[nt][e] = 0.f;

#pragma unroll
    for (int nt = 0; nt < 14; nt++) {
        const int pos0 = nt * WINX + bx0;
        unsigned bh0, bh1, bh2, bh3, bl0, bl1, bl2, bl3;
        ldmx4(bh0, bh1, bh2, bh3, &skh[(pos0 + lrow) * PQK + kcol]);
        ldmx4(bl0, bl1, bl2, bl3, &skl[(pos0 + lrow) * PQK + kcol]);
        float* d = acc[nt];
        mma16816(d[0], d[1], d[2], d[3], qa_h[0][0], qa_h[0][1], qa_h[0][2], qa_h[0][3], bh0, bh1);
        mma16816(d[0], d[1], d[2], d[3], qa_h[1][0], qa_h[1][1], qa_h[1][2], qa_h[1][3], bh2, bh3);
        mma16816(d[0], d[1], d[2], d[3], qa_h[0][0], qa_h[0][1], qa_h[0][2], qa_h[0][3], bl0, bl1);
        mma16816(d[0], d[1], d[2], d[3], qa_h[1][0], qa_h[1][1], qa_h[1][2], qa_h[1][3], bl2, bl3);
        mma16816(d[0], d[1], d[2], d[3], qa_l[0][0], qa_l[0][1], qa_l[0][2], qa_l[0][3], bh0, bh1);
        mma16816(d[0], d[1], d[2], d[3], qa_l[1][0], qa_l[1][1], qa_l[1][2], qa_l[1][3], bh2, bh3);
    }

    // ---- masked softmax (rows r0/r1 share y -> shared jy test) ----
    float mx0 = -1e30f, mx1 = -1e30f;
#pragma unroll
    for (int nt = 0; nt < 14; nt++) {
        const bool oky = (unsigned)(nt - vy) < 7u;
#pragma unroll
        for (int e = 0; e < 2; e++) {
            const int jx = 2 * t4 + e;
            bool ok0 = oky && ((unsigned)(jx - vx0) < 7u);
            bool ok1 = oky && ((unsigned)(jx - vx1) < 7u);
            acc[nt][e]     = ok0 ? acc[nt][e]     : -1e30f;
            acc[nt][2 + e] = ok1 ? acc[nt][2 + e] : -1e30f;
            mx0 = fmaxf(mx0, acc[nt][e]);
            mx1 = fmaxf(mx1, acc[nt][2 + e]);
        }
    }
    mx0 = fmaxf(mx0, __shfl_xor_sync(0xffffffffu, mx0, 1));
    mx0 = fmaxf(mx0, __shfl_xor_sync(0xffffffffu, mx0, 2));
    mx1 = fmaxf(mx1, __shfl_xor_sync(0xffffffffu, mx1, 1));
    mx1 = fmaxf(mx1, __shfl_xor_sync(0xffffffffu, mx1, 2));

    float sum0 = 0.f, sum1 = 0.f;
#pragma unroll
    for (int nt = 0; nt < 14; nt++) {
#pragma unroll
        for (int e = 0; e < 2; e++) {
            float p0 = __expf(acc[nt][e] - mx0);
            float p1 = __expf(acc[nt][2 + e] - mx1);
            acc[nt][e] = p0; acc[nt][2 + e] = p1;
            sum0 += p0; sum1 += p1;
        }
    }
    sum0 += __shfl_xor_sync(0xffffffffu, sum0, 1);
    sum0 += __shfl_xor_sync(0xffffffffu, sum0, 2);
    sum1 += __shfl_xor_sync(0xffffffffu, sum1, 1);
    sum1 += __shfl_xor_sync(0xffffffffu, sum1, 2);
    const float inv0 = 1.0f / sum0, inv1 = 1.0f / sum1;

    // ---- convert P in place to packed bf16 hi/lo A-fragments ----
#pragma unroll
    for (int nt = 0; nt < 14; nt++) {
        float p00 = acc[nt][0], p01 = acc[nt][1];
        float p10 = acc[nt][2], p11 = acc[nt][3];
        unsigned hh0 = pack2bf(p00, p01);
        unsigned hh1 = pack2bf(p10, p11);
        unsigned ll0 = pack2bf(bf_res(p00), bf_res(p01));
        unsigned ll1 = pack2bf(bf_res(p10), bf_res(p11));
        acc[nt][0] = __uint_as_float(hh0);
        acc[nt][1] = __uint_as_float(hh1);
        acc[nt][2] = __uint_as_float(ll0);
        acc[nt][3] = __uint_as_float(ll1);
    }

    cp_wait<0>();     // V staged
    __syncthreads();

    // ---- PV MMA: 7 k-tiles of 16 positions (2 window rows each) ----
    float o[4][4];
#pragma unroll
    for (int vt = 0; vt < 4; vt++)
#pragma unroll
        for (int e = 0; e < 4; e++) o[vt][e] = 0.f;

    const int vrow = (lmat & 1) * 8 + lrow;     // k-row index 0..15 within tile
    const int vmat = (lmat >> 1) * 8;           // col sub-offset
#pragma unroll
    for (int kt = 0; kt < 7; kt++) {
        // this lane's position for k-row vrow of tile kt
        const int jy = 2 * kt + (vrow >> 3);
        const int prow = jy * WINX + bx0 + (vrow & 7);
        unsigned ah0 = __float_as_uint(acc[2 * kt][0]);
        unsigned ah1 = __float_as_uint(acc[2 * kt][1]);
        unsigned ah2 = __float_as_uint(acc[2 * kt + 1][0]);
        unsigned ah3 = __float_as_uint(acc[2 * kt + 1][1]);
        unsigned al0 = __float_as_uint(acc[2 * kt][2]);
        unsigned al1 = __float_as_uint(acc[2 * kt][3]);
        unsigned al2 = __float_as_uint(acc[2 * kt + 1][2]);
        unsigned al3 = __float_as_uint(acc[2 * kt + 1][3]);
#pragma unroll
        for (int half = 0; half < 2; half++) {
            unsigned bh0, bh1, bh2, bh3, bl0, bl1, bl2, bl3;
            const int col = half * 16 + vmat;
            ldmx4t(bh0, bh1, bh2, bh3, &svh[prow * PQK + col]);
            ldmx4t(bl0, bl1, bl2, bl3, &svl[prow * PQK + col]);
            float* d0 = o[2 * half];
            float* d1 = o[2 * half + 1];
            mma16816(d0[0], d0[1], d0[2], d0[3], ah0, ah1, ah2, ah3, bh0, bh1);
            mma16816(d0[0], d0[1], d0[2], d0[3], ah0, ah1, ah2, ah3, bl0, bl1);
            mma16816(d0[0], d0[1], d0[2], d0[3], al0, al1, al2, al3, bh0, bh1);
            mma16816(d1[0], d1[1], d1[2], d1[3], ah0, ah1, ah2, ah3, bh2, bh3);
            mma16816(d1[0], d1[1], d1[2], d1[3], ah0, ah1, ah2, ah3, bl2, bl3);
            mma16816(d1[0], d1[1], d1[2], d1[3], al0, al1, al2, al3, bh2, bh3);
        }
    }

    // ---- epilogue: normalize, split, store [s][h*32+d] ----
    {
        size_t s0 = (size_t)(qyg * W_ + qxg0) * CIN + h * DH;
        size_t s1 = s0 + CIN;   // query x+1
#pragma unroll
        for (int vt = 0; vt < 4; vt++) {
            int c = vt * 8 + 2 * t4;
            float f00 = o[vt][0] * inv0, f01 = o[vt][1] * inv0;
            float f10 = o[vt][2] * inv1, f11 = o[vt][3] * inv1;
            *(unsigned*)&g_ahi[s0 + c] = pack2bf(f00, f01);
            *(unsigned*)&g_alo[s0 + c] = pack2bf(bf_res(f00), bf_res(f01));
            *(unsigned*)&g_ahi[s1 + c] = pack2bf(f10, f11);
            *(unsigned*)&g_alo[s1 + c] = pack2bf(bf_res(f10), bf_res(f11));
        }
    }
}

// ---------------------------------------------------------------------------
extern "C" void kernel_launch(void* const* d_in, const int* in_sizes, int n_in,
                              void* d_out, int out_size)
{
    const float* x     = (const float*)d_in[0];   // [256][9216]
    const float* w_qkv = (const float*)d_in[1];   // [768][256]
    const float* b_qkv = (const float*)d_in[2];   // [768]
    const float* w_out = (const float*)d_in[3];   // [256][256]
    const float* b_out = (const float*)d_in[4];   // [256]
    float* out = (float*)d_out;                   // [256][9216]

    cudaFuncSetAttribute(natten_mma,
                         cudaFuncAttributeMaxDynamicSharedMemorySize, NATTEN_SMEM);

    split_all_kernel<<<NBX + 64, 256>>>(x, w_qkv, w_out);

    __nv_bfloat16 *xhi, *xlo, *wqhi, *wqlo, *wohi, *wolo, *ahi, *alo;
    cudaGetSymbolAddress((void**)&xhi,  g_xhi);
    cudaGetSymbolAddress((void**)&xlo,  g_xlo);
    cudaGetSymbolAddress((void**)&wqhi, g_wqhi);
    cudaGetSymbolAddress((void**)&wqlo, g_wqlo);
    cudaGetSymbolAddress((void**)&wohi, g_wohi);
    cudaGetSymbolAddress((void**)&wolo, g_wolo);
    cudaGetSymbolAddress((void**)&ahi,  g_ahi);
    cudaGetSymbolAddress((void**)&alo,  g_alo);

    // qkv: M = s (128-tiles, 72), N = 768 channels (128-tiles, 6)
    gemm_bf16x3<128, 0><<<dim3(S_ / 128, 768 / 128), 256>>>(
        xhi, xlo, wqhi, wqlo, b_qkv, nullptr);

    natten_mma<<<dim3(W_ / TQX, H_ / TQY, NH), 256, NATTEN_SMEM>>>();

    // out: M = s (128-tiles, 72), N = cout (64-tiles, 4) -> round-7 config
    gemm_bf16x3<64, 1><<<dim3(S_ / 128, CIN / 64), 256>>>(
        ahi, alo, wohi, wolo, b_out, out);
}